// round 4
// baseline (speedup 1.0000x reference)
#include <cuda_runtime.h>

#define NS 25
#define NC 80
#define CD (NC*NC)          // 6400
#define BATCH 64
#define TIME 400
#define BT (BATCH*TIME)     // 25600
#define M_ELEMS (BT*NC)     // 2,048,000

#define R 32                // bt rows per tile
#define NTILES (BT / R)     // 800
#define CTHREADS 640        // 2 row-groups x 320 column-threads
#define COLS4 320           // float4 columns per block
#define RPT 16              // rows per thread
#define YBLKS 29            // 5 * 29 = 145 blocks -> single wave

__device__ __forceinline__ void ffma2(unsigned long long &acc,
                                      unsigned long long a,
                                      unsigned long long b) {
    asm("fma.rn.f32x2 %0, %1, %2, %0;" : "+l"(acc) : "l"(a), "l"(b));
}

__device__ __forceinline__ float softplus_f(float x) { return log1pf(expf(x)); }

// ---------------------------------------------------------------------------
// Persistent fused kernel, grid = (5, YBLKS), 640 threads.
// Thread t: row-group g = t/320 (rows g*16..g*16+15), column ct = t%320,
// col4 = bx*320 + ct. D slice (128 KB per x-chunk) stays L1-resident.
// ---------------------------------------------------------------------------
__global__ __launch_bounds__(CTHREADS, 1)
void fused_kernel(const float* __restrict__ alpha,
                  const float* __restrict__ mu,
                  const float* __restrict__ D,
                  const float* __restrict__ asc,
                  float* __restrict__ m_out,
                  float* __restrict__ C)
{
    __shared__ float scale_s[NS];
    __shared__ __align__(16) unsigned long long a2s[NS * R];  // [j][r] {a,a}
    __shared__ float mu_s[NS * NC];                           // x==0 only

    const int tid = threadIdx.x;
    const bool do_m = (blockIdx.x == 0);

    if (tid < NS) scale_s[tid] = softplus_f(asc[tid]);
    if (do_m) {
        for (int i = tid; i < NS * NC; i += CTHREADS) mu_s[i] = mu[i];
    }

    const int grp = tid / COLS4;                 // 0 or 1
    const int ct  = tid - grp * COLS4;           // 0..319
    const int r0  = grp * RPT;                   // first row of this thread
    const int col4 = blockIdx.x * COLS4 + ct;
    const char* Dbase = reinterpret_cast<const char*>(D) + (size_t)col4 * 16;

    // alpha-prefetch indices: flat tile index i enumerates (r,j), i = r*NS+j
    const int i0 = tid;                          // < 640
    const int i1 = tid + CTHREADS;               // < 800 only for tid < 160
    const int j_0 = i0 % NS, rr0 = i0 / NS;
    const int j_1 = i1 % NS, rr1 = i1 / NS;
    const bool has1 = (i1 < R * NS);

    // preload first tile's alpha
    int yt = blockIdx.y;
    float pa0 = 0.f, pa1 = 0.f;
    if (yt < NTILES) {
        const float* ap = alpha + (size_t)yt * (R * NS);
        pa0 = ap[i0];
        if (has1) pa1 = ap[i1];
    }

    for (; yt < NTILES; yt += YBLKS) {
        const int bt0 = yt * R;

        __syncthreads();   // previous tile's a2s readers done (and scale_s ready)
        a2s[j_0 * R + rr0] = [&]{
            const float v = pa0 * scale_s[j_0];
            float2 p = make_float2(v, v);
            return *reinterpret_cast<unsigned long long*>(&p);
        }();
        if (has1) {
            const float v = pa1 * scale_s[j_1];
            float2 p = make_float2(v, v);
            a2s[j_1 * R + rr1] = *reinterpret_cast<unsigned long long*>(&p);
        }
        __syncthreads();

        // prefetch next tile's alpha (overlaps with compute below)
        if (yt + YBLKS < NTILES) {
            const float* ap = alpha + (size_t)(yt + YBLKS) * (R * NS);
            pa0 = ap[i0];
            if (has1) pa1 = ap[i1];
        }

        // ---------------- C tile: 16 rows x 4 cols per thread ----------------
        unsigned long long acc[RPT][2];
        #pragma unroll
        for (int r = 0; r < RPT; r++) { acc[r][0] = 0ull; acc[r][1] = 0ull; }

        #pragma unroll 5
        for (int j = 0; j < NS; j++) {
            const ulonglong2 d =
                *reinterpret_cast<const ulonglong2*>(Dbase + (size_t)j * (CD * 4));
            #pragma unroll
            for (int r2 = 0; r2 < RPT; r2 += 2) {
                const ulonglong2 aa =
                    *reinterpret_cast<const ulonglong2*>(&a2s[j * R + r0 + r2]);
                ffma2(acc[r2    ][0], d.x, aa.x);
                ffma2(acc[r2    ][1], d.y, aa.x);
                ffma2(acc[r2 + 1][0], d.x, aa.y);
                ffma2(acc[r2 + 1][1], d.y, aa.y);
            }
        }

        float* Cbase = C + (size_t)(bt0 + r0) * CD + (size_t)col4 * 4;
        #pragma unroll
        for (int r = 0; r < RPT; r++) {
            ulonglong2 u;
            u.x = acc[r][0];
            u.y = acc[r][1];
            __stcs(reinterpret_cast<float4*>(Cbase + (size_t)r * CD),
                   *reinterpret_cast<float4*>(&u));
        }

        // ---------------- m tile (x==0 blocks only) ----------------
        if (do_m) {
            for (int o = tid; o < R * NC; o += CTHREADS) {
                const int r = o / NC, c = o % NC;
                float s = 0.0f;
                #pragma unroll
                for (int j = 0; j < NS; j++) {
                    const float a = reinterpret_cast<const float2*>(&a2s[j * R + r])->x;
                    s = fmaf(a, mu_s[j * NC + c], s);
                }
                __stcs(&m_out[(size_t)(bt0 + r) * NC + c], s);
            }
        }
    }
}

extern "C" void kernel_launch(void* const* d_in, const int* in_sizes, int n_in,
                              void* d_out, int out_size)
{
    const float* alpha = (const float*)d_in[0];   // [64,400,25]
    const float* mu    = (const float*)d_in[1];   // [25,80]
    const float* D     = (const float*)d_in[2];   // [25,80,80]
    const float* asc   = (const float*)d_in[3];   // [25]

    float* out = (float*)d_out;
    float* m_out = out;                 // [64,400,80]
    float* c_out = out + M_ELEMS;       // [64,400,80,80]

    fused_kernel<<<dim3(5, YBLKS), CTHREADS>>>(alpha, mu, D, asc, m_out, c_out);
}

// round 5
// speedup vs baseline: 1.0220x; 1.0220x over previous
#include <cuda_runtime.h>

#define NS 25
#define NC 80
#define CD (NC*NC)          // 6400
#define BATCH 64
#define TIME 400
#define BT (BATCH*TIME)     // 25600

#define RPT 16              // rows per tile (= rows per thread)
#define NTILES (BT / RPT)   // 1600
#define CTHREADS 320        // 320 thr * 4 floats = 1280 cols
#define YBLKS 58            // 5 * 58 = 290 blocks = 2 per SM, single wave

__device__ __forceinline__ void ffma2(unsigned long long &acc,
                                      unsigned long long a,
                                      unsigned long long b) {
    asm("fma.rn.f32x2 %0, %1, %2, %0;" : "+l"(acc) : "l"(a), "l"(b));
}

__device__ __forceinline__ float softplus_f(float x) { return log1pf(expf(x)); }

// ---------------------------------------------------------------------------
// Persistent fused kernel, grid = (5, YBLKS), 320 threads, 2 blocks/SM.
// Block (x,y): float4 columns [x*320, x*320+320), tiles yt = y, y+YBLKS, ...
// Each tile = 16 bt-rows x 1280 cols; thread owns 16 rows x 1 float4 col.
// Two co-resident blocks de-phase load/compute/store phases.
// ---------------------------------------------------------------------------
__global__ __launch_bounds__(CTHREADS, 2)
void fused_kernel(const float* __restrict__ alpha,
                  const float* __restrict__ mu,
                  const float* __restrict__ D,
                  const float* __restrict__ asc,
                  float* __restrict__ m_out,
                  float* __restrict__ C)
{
    __shared__ float scale_s[NS];
    __shared__ __align__(16) unsigned long long a2s[NS * RPT];  // [j][r] {a,a}
    __shared__ float mu_s[NS * NC];                             // x==0 only

    const int tid = threadIdx.x;
    const bool do_m = (blockIdx.x == 0);

    if (tid < NS) scale_s[tid] = softplus_f(asc[tid]);
    if (do_m) {
        for (int i = tid; i < NS * NC; i += CTHREADS) mu_s[i] = mu[i];
    }

    const int col4 = blockIdx.x * CTHREADS + tid;
    const char* Dbase = reinterpret_cast<const char*>(D) + (size_t)col4 * 16;

    // alpha prefetch: tile has RPT*NS = 400 entries; i = r*NS + j
    const int i0 = tid;                    // all 320
    const int i1 = tid + CTHREADS;         // threads < 80
    const int j_0 = i0 % NS, rr0 = i0 / NS;
    const int j_1 = i1 % NS, rr1 = i1 / NS;
    const bool has1 = (i1 < RPT * NS);

    int yt = blockIdx.y;
    float pa0 = 0.f, pa1 = 0.f;
    if (yt < NTILES) {
        const float* ap = alpha + (size_t)yt * (RPT * NS);
        pa0 = ap[i0];
        if (has1) pa1 = ap[i1];
    }

    for (; yt < NTILES; yt += YBLKS) {
        const int bt0 = yt * RPT;

        __syncthreads();   // prior tile's a2s readers done (and scale_s, iter 0)
        {
            const float v = pa0 * scale_s[j_0];
            float2 p = make_float2(v, v);
            a2s[j_0 * RPT + rr0] = *reinterpret_cast<unsigned long long*>(&p);
        }
        if (has1) {
            const float v = pa1 * scale_s[j_1];
            float2 p = make_float2(v, v);
            a2s[j_1 * RPT + rr1] = *reinterpret_cast<unsigned long long*>(&p);
        }
        __syncthreads();

        // prefetch next tile's alpha (overlaps compute)
        if (yt + YBLKS < NTILES) {
            const float* ap = alpha + (size_t)(yt + YBLKS) * (RPT * NS);
            pa0 = ap[i0];
            if (has1) pa1 = ap[i1];
        }

        // ---------------- C tile: 16 rows x 4 cols per thread ----------------
        unsigned long long acc[RPT][2];
        #pragma unroll
        for (int r = 0; r < RPT; r++) { acc[r][0] = 0ull; acc[r][1] = 0ull; }

        #pragma unroll 5
        for (int j = 0; j < NS; j++) {
            const ulonglong2 d =
                *reinterpret_cast<const ulonglong2*>(Dbase + (size_t)j * (CD * 4));
            #pragma unroll
            for (int r2 = 0; r2 < RPT; r2 += 2) {
                const ulonglong2 aa =
                    *reinterpret_cast<const ulonglong2*>(&a2s[j * RPT + r2]);
                ffma2(acc[r2    ][0], d.x, aa.x);
                ffma2(acc[r2    ][1], d.y, aa.x);
                ffma2(acc[r2 + 1][0], d.x, aa.y);
                ffma2(acc[r2 + 1][1], d.y, aa.y);
            }
        }

        float* Cbase = C + (size_t)bt0 * CD + (size_t)col4 * 4;
        #pragma unroll
        for (int r = 0; r < RPT; r++) {
            ulonglong2 u;
            u.x = acc[r][0];
            u.y = acc[r][1];
            __stcs(reinterpret_cast<float4*>(Cbase + (size_t)r * CD),
                   *reinterpret_cast<float4*>(&u));
        }

        // ---------------- m tile (x==0 blocks only) ----------------
        if (do_m) {
            #pragma unroll
            for (int o = tid; o < RPT * NC; o += CTHREADS) {
                const int r = o / NC, c = o % NC;
                float s = 0.0f;
                #pragma unroll
                for (int j = 0; j < NS; j++) {
                    const float a = reinterpret_cast<const float2*>(&a2s[j * RPT + r])->x;
                    s = fmaf(a, mu_s[j * NC + c], s);
                }
                __stcs(&m_out[(size_t)(bt0 + r) * NC + c], s);
            }
        }
    }
}

extern "C" void kernel_launch(void* const* d_in, const int* in_sizes, int n_in,
                              void* d_out, int out_size)
{
    const float* alpha = (const float*)d_in[0];   // [64,400,25]
    const float* mu    = (const float*)d_in[1];   // [25,80]
    const float* D     = (const float*)d_in[2];   // [25,80,80]
    const float* asc   = (const float*)d_in[3];   // [25]

    float* out = (float*)d_out;
    float* m_out = out;                  // [64,400,80]
    float* c_out = out + (BT * NC);      // [64,400,80,80]

    fused_kernel<<<dim3(5, YBLKS), CTHREADS>>>(alpha, mu, D, asc, m_out, c_out);
}